// round 1
// baseline (speedup 1.0000x reference)
#include <cuda_runtime.h>
#include <cuda_bf16.h>
#include <cstdint>

// Problem constants
#define N_NODES 8192
#define F_DIM   256
#define K_KEEP  4096
#define KDIM    8192   // GEMM K dimension

// ---------------- scratch (__device__ globals; no allocs allowed) ----------
__device__ float          g_y[N_NODES];
__device__ unsigned char  g_keep[N_NODES];
__device__ int            g_idx[K_KEEP];
__device__ int            g_pos[N_NODES];
__device__ __nv_bfloat16  g_Arows[(size_t)K_KEEP * KDIM];   // A[idx[r], k]  (M,K) K-major
__device__ __nv_bfloat16  g_Bmat [(size_t)K_KEEP * KDIM];   // A[k, idx[c]]  (N,K) K-major

// ---------------- PTX helpers ----------------------------------------------
__device__ __forceinline__ void cp_async16(uint32_t saddr, const void* gaddr) {
    asm volatile("cp.async.cg.shared.global [%0], [%1], 16;\n" :: "r"(saddr), "l"(gaddr));
}
__device__ __forceinline__ void cp_commit() {
    asm volatile("cp.async.commit_group;\n" ::);
}
__device__ __forceinline__ void ldsm4(uint32_t& r0, uint32_t& r1, uint32_t& r2, uint32_t& r3,
                                      uint32_t addr) {
    asm volatile("ldmatrix.sync.aligned.m8n8.x4.shared.b16 {%0,%1,%2,%3}, [%4];\n"
                 : "=r"(r0), "=r"(r1), "=r"(r2), "=r"(r3) : "r"(addr));
}
__device__ __forceinline__ void mma16816(float* c, const uint32_t* a, const uint32_t* b) {
    asm volatile("mma.sync.aligned.m16n8k16.row.col.f32.bf16.bf16.f32 "
                 "{%0,%1,%2,%3}, {%4,%5,%6,%7}, {%8,%9}, {%0,%1,%2,%3};\n"
                 : "+f"(c[0]), "+f"(c[1]), "+f"(c[2]), "+f"(c[3])
                 : "r"(a[0]), "r"(a[1]), "r"(a[2]), "r"(a[3]), "r"(b[0]), "r"(b[1]));
}

// ---------------- 1. y = (X @ p) * rsqrt(sum(p^2)) --------------------------
// 256 threads/block; 8 warps -> 8 rows per block; grid = 1024
__global__ void compute_y_kernel(const float* __restrict__ X, const float* __restrict__ p) {
    __shared__ float sp[F_DIM];
    __shared__ float red[8];
    int t = threadIdx.x;
    sp[t] = p[t];
    __syncthreads();
    float v = sp[t] * sp[t];
    #pragma unroll
    for (int o = 16; o; o >>= 1) v += __shfl_xor_sync(0xffffffffu, v, o);
    if ((t & 31) == 0) red[t >> 5] = v;
    __syncthreads();
    float sumsq = 0.f;
    #pragma unroll
    for (int w = 0; w < 8; ++w) sumsq += red[w];
    float inv = rsqrtf(sumsq);

    int wid = t >> 5, lane = t & 31;
    int row = blockIdx.x * 8 + wid;
    const float* xr = X + (size_t)row * F_DIM;
    float acc = 0.f;
    #pragma unroll
    for (int u = 0; u < 8; ++u) acc += xr[lane + 32 * u] * sp[lane + 32 * u];
    #pragma unroll
    for (int o = 16; o; o >>= 1) acc += __shfl_xor_sync(0xffffffffu, acc, o);
    if (lane == 0) g_y[row] = acc * inv;
}

// ---------------- 2. rank-based top-k: keep[i] = rank(y[i]) < K -------------
// grid = 32 blocks x 256 threads; each thread one i; full y in smem
__global__ void rank_kernel() {
    __shared__ float sy[N_NODES];
    int t = threadIdx.x;
    for (int j = t; j < N_NODES; j += 256) sy[j] = g_y[j];
    __syncthreads();
    int i = blockIdx.x * 256 + t;
    float yi = sy[i];
    int cnt = 0;
    #pragma unroll 8
    for (int j = 0; j < N_NODES; ++j) {
        float v = sy[j];
        cnt += (int)((v > yi) || (v == yi && j < i));
    }
    g_keep[i] = (cnt < K_KEEP) ? 1 : 0;
}

// ---------------- 3. compact (stable, ascending) -> idx / pos --------------
// single block of 1024 threads; each handles 8 consecutive elements
__global__ void compact_kernel() {
    __shared__ int s[1024];
    int t = threadIdx.x;
    int base = t * 8;
    int flags[8];
    int c = 0;
    #pragma unroll
    for (int u = 0; u < 8; ++u) { flags[u] = g_keep[base + u]; c += flags[u]; }
    s[t] = c;
    __syncthreads();
    // Hillis-Steele inclusive scan
    for (int off = 1; off < 1024; off <<= 1) {
        int add = (t >= off) ? s[t - off] : 0;
        __syncthreads();
        s[t] += add;
        __syncthreads();
    }
    int pos = s[t] - c;   // exclusive prefix
    #pragma unroll
    for (int u = 0; u < 8; ++u) {
        int i = base + u;
        if (flags[u]) { g_idx[pos] = i; g_pos[i] = pos; ++pos; }
        else          { g_pos[i] = -1; }
    }
}

// ---------------- 4. X_pooled[r,f] = X[idx[r],f] * tanh(y[idx[r]]) ----------
__global__ void xpool_kernel(const float* __restrict__ X, float* __restrict__ outX) {
    int r = blockIdx.x;
    int i = g_idx[r];
    float g = tanhf(g_y[i]);
    outX[(size_t)r * F_DIM + threadIdx.x] = X[(size_t)i * F_DIM + threadIdx.x] * g;
}

// ---------------- 5a. Arows[r,k] = bf16(A[idx[r],k]) ------------------------
__global__ void gatherA_kernel(const float* __restrict__ A) {
    int r = blockIdx.x;
    int src = g_idx[r];
    const float4* arow = (const float4*)(A + (size_t)src * KDIM);
    __nv_bfloat162* drow = (__nv_bfloat162*)(g_Arows + (size_t)r * KDIM);
    for (int c = threadIdx.x; c < KDIM / 4; c += 256) {
        float4 v = arow[c];
        drow[c * 2 + 0] = __floats2bfloat162_rn(v.x, v.y);
        drow[c * 2 + 1] = __floats2bfloat162_rn(v.z, v.w);
    }
}

// ---------------- 5b. Bmat[pos[j],k] = bf16(A[k,j]) (tiled transpose) -------
// grid (128,128): x -> k tile, y -> j tile; 64x64 tiles via smem
__global__ void gatherB_kernel(const float* __restrict__ A) {
    __shared__ float tile[64][65];
    int k0 = blockIdx.x * 64, j0 = blockIdx.y * 64;
    int t = threadIdx.x;
    #pragma unroll
    for (int i = 0; i < 16; ++i) {
        int lin = t + 256 * i;
        int r = lin >> 6, c = lin & 63;
        tile[r][c] = A[(size_t)(k0 + r) * N_NODES + j0 + c];
    }
    __syncthreads();
    #pragma unroll
    for (int i = 0; i < 16; ++i) {
        int lin = t + 256 * i;
        int c = lin >> 6, r = lin & 63;
        int p = g_pos[j0 + c];
        if (p >= 0)
            g_Bmat[(size_t)p * KDIM + k0 + r] = __float2bfloat16(tile[r][c]);
    }
}

// ---------------- 6. GEMM: C[4096,4096] = Arows @ Bmat^T (bf16 -> f32) ------
// BM=BN=128, BK=64, 256 threads, 2x4 warps, warp tile 64x32, m16n8k16
__global__ void gemm_kernel(float* __restrict__ C) {
    extern __shared__ char smem[];
    const int t = threadIdx.x;
    const int lane = t & 31, wid = t >> 5;
    const int wm = wid >> 2, wn = wid & 3;
    const int bm = blockIdx.y, bn = blockIdx.x;

    const __nv_bfloat16* Ag = g_Arows + (size_t)bm * 128 * KDIM;
    const __nv_bfloat16* Bg = g_Bmat  + (size_t)bn * 128 * KDIM;

    uint32_t smem_base = (uint32_t)__cvta_generic_to_shared(smem);

    auto load_tile = [&](int kt, int stage) {
        uint32_t sA = smem_base + stage * 32768;
        uint32_t sB = sA + 16384;
        #pragma unroll
        for (int i = 0; i < 4; ++i) {
            int lin = t + 256 * i;             // 1024 16B chunks per operand
            int row = lin >> 3, chunk = lin & 7;
            int sw = chunk ^ (row & 7);
            cp_async16(sA + row * 128 + sw * 16,
                       Ag + (size_t)row * KDIM + kt * 64 + chunk * 8);
            cp_async16(sB + row * 128 + sw * 16,
                       Bg + (size_t)row * KDIM + kt * 64 + chunk * 8);
        }
        cp_commit();
    };

    float c[4][4][4] = {};

    load_tile(0, 0);
    const int KT = KDIM / 64;
    for (int kt = 0; kt < KT; ++kt) {
        if (kt + 1 < KT) {
            load_tile(kt + 1, (kt + 1) & 1);
            asm volatile("cp.async.wait_group 1;\n" ::);
        } else {
            asm volatile("cp.async.wait_group 0;\n" ::);
        }
        __syncthreads();

        uint32_t sA = smem_base + (kt & 1) * 32768;
        uint32_t sB = sA + 16384;
        #pragma unroll
        for (int ks = 0; ks < 4; ++ks) {
            uint32_t a[4][4], b[4][2];
            #pragma unroll
            for (int mt = 0; mt < 4; ++mt) {
                int row = wm * 64 + mt * 16 + (lane & 15);
                int chunk = ks * 2 + (lane >> 4);
                int sw = chunk ^ (row & 7);
                ldsm4(a[mt][0], a[mt][1], a[mt][2], a[mt][3], sA + row * 128 + sw * 16);
            }
            #pragma unroll
            for (int pr = 0; pr < 2; ++pr) {
                int row = wn * 32 + pr * 16 + ((lane >> 4) & 1) * 8 + (lane & 7);
                int chunk = ks * 2 + ((lane >> 3) & 1);
                int sw = chunk ^ (row & 7);
                ldsm4(b[pr * 2][0], b[pr * 2][1], b[pr * 2 + 1][0], b[pr * 2 + 1][1],
                      sB + row * 128 + sw * 16);
            }
            #pragma unroll
            for (int mt = 0; mt < 4; ++mt)
                #pragma unroll
                for (int nt = 0; nt < 4; ++nt)
                    mma16816(c[mt][nt], a[mt], b[nt]);
        }
        __syncthreads();
    }

    // epilogue
    int groupId = lane >> 2, tid4 = lane & 3;
    #pragma unroll
    for (int mt = 0; mt < 4; ++mt) {
        int row0 = bm * 128 + wm * 64 + mt * 16 + groupId;
        #pragma unroll
        for (int nt = 0; nt < 4; ++nt) {
            int col = bn * 128 + wn * 32 + nt * 8 + tid4 * 2;
            *(float2*)(C + (size_t)row0 * K_KEEP + col)       = make_float2(c[mt][nt][0], c[mt][nt][1]);
            *(float2*)(C + (size_t)(row0 + 8) * K_KEEP + col) = make_float2(c[mt][nt][2], c[mt][nt][3]);
        }
    }
}

// ---------------- launch -----------------------------------------------------
extern "C" void kernel_launch(void* const* d_in, const int* in_sizes, int n_in,
                              void* d_out, int out_size) {
    const float* X = (const float*)d_in[0];   // (8192, 256)
    const float* A = (const float*)d_in[1];   // (8192, 8192)
    const float* p = (const float*)d_in[2];   // (256, 1)

    float* out  = (float*)d_out;
    float* outX = out;                                  // (4096, 256)
    float* outA = out + (size_t)K_KEEP * F_DIM;         // (4096, 4096)

    compute_y_kernel<<<N_NODES / 8, 256>>>(X, p);
    rank_kernel<<<N_NODES / 256, 256>>>();
    compact_kernel<<<1, 1024>>>();
    xpool_kernel<<<K_KEEP, F_DIM>>>(X, outX);
    gatherA_kernel<<<K_KEEP, 256>>>(A);
    gatherB_kernel<<<dim3(N_NODES / 64, N_NODES / 64), 256>>>(A);

    cudaFuncSetAttribute(gemm_kernel, cudaFuncAttributeMaxDynamicSharedMemorySize, 65536);
    gemm_kernel<<<dim3(K_KEEP / 128, K_KEEP / 128), 256, 65536>>>(outA);
}